// round 4
// baseline (speedup 1.0000x reference)
#include <cuda_runtime.h>
#include <cstdint>

#define BSZ 512
#define TSZ 512
#define FF  64
#define UU  512
#define PP  32
#define K1P 640                 // 512 hs | 64 x | 32 acc | 32 zero-pad
#define NCTA 128
#define NTHR 256
#define KC   16
#define NSPL 8                  // split-K factor

// ---------------- device-global scratch ----------------
__device__ float g_W0[K1P * UU];       // [640,512] rows: WA0 | WB0(x) | WB0(acc) | 0
__device__ float g_W1[2 * UU * UU];    // rows 0-511 WA1, 512-1023 E1=WC0@WBr0
__device__ float g_W2[2 * UU * UU];    // rows 0-511 WA2, 512-1023 E2=WC1@WBr1
__device__ float g_Wo[UU * PP];        // Eo = WC2@Wout
__device__ float g_c0[UU], g_c1[UU], g_c2[UU], g_co[PP];
__device__ float g_NS[3][NSPL][BSZ * UU];  // split-K partials per layer
__device__ float g_HM[3][BSZ * UU];        // merged states (= hs for next step)
__device__ float g_ACC[BSZ * PP];
__device__ unsigned g_bar;

// ---------------- FFMA2 helpers ----------------
__device__ __forceinline__ void fma2(unsigned long long& d, unsigned long long a,
                                     unsigned long long b) {
    asm("fma.rn.f32x2 %0, %1, %2, %0;" : "+l"(d) : "l"(a), "l"(b));
}
__device__ __forceinline__ void unpack2(unsigned long long v, float& lo, float& hi) {
    asm("mov.b64 {%0, %1}, %2;" : "=f"(lo), "=f"(hi) : "l"(v));
}

// ---------------- grid barrier (128 CTAs, single wave) ----------------
__device__ __forceinline__ void gsync(unsigned& barn) {
    barn += 1;
    const unsigned target = barn * NCTA;
    __syncthreads();
    if (threadIdx.x == 0) {
        __threadfence();
        atomicAdd(&g_bar, 1u);
        unsigned v;
        do {
            asm volatile("ld.acquire.gpu.u32 %0, [%1];" : "=r"(v) : "l"(&g_bar) : "memory");
            if (v >= target) break;
            __nanosleep(32);
        } while (true);
    }
    __syncthreads();
}

// ---------------- A-operand fetch (merged across split-K partials) ----------
__device__ __forceinline__ float4 loadA(int phase, int b, int k, int t,
                                        const float* __restrict__ x, bool wb) {
    float4 v;
    if (phase == 1) {
        if (k < UU)
            v = __ldcg((const float4*)&g_HM[0][b * UU + k]);
        else if (k < UU + FF)
            v = __ldg((const float4*)&x[((size_t)b * TSZ + t) * FF + (k - UU)]);
        else if (k < UU + FF + PP)
            v = __ldcg((const float4*)&g_ACC[b * PP + (k - UU - FF)]);
        else
            v = make_float4(0.f, 0.f, 0.f, 0.f);
    } else {
        if (k < UU) {
            v = __ldcg((const float4*)&g_HM[phase - 1][b * UU + k]);
        } else {
            const int off = b * UU + (k - UU);
            const float(*P)[BSZ * UU] = g_NS[phase - 2];
            v = __ldcg((const float4*)&P[0][off]);
#pragma unroll
            for (int s = 1; s < NSPL; s++) {
                const float4 w = __ldcg((const float4*)&P[s][off]);
                v.x += w.x; v.y += w.y; v.z += w.z; v.w += w.w;
            }
            if (wb) *(float4*)&g_HM[phase - 2][off] = v;  // piggyback merge
        }
    }
    return v;
}

// ---------------- main GEMM phase: tile 128x128, split-K 8 ------------------
// smem: As2 [2][KC][256] dup pairs (8192 f) then Bs [2][KC][128] (4096 f)
__device__ void phase_gemm(float* sm, int phase, int t, const float* __restrict__ x,
                           const float* __restrict__ W, const float* __restrict__ cb,
                           int Ktot, float* __restrict__ dst_base) {
    const int tid = threadIdx.x;
    const int cta = blockIdx.x;
    const int s   = cta & 7;
    const int nt  = (cta >> 3) & 3;
    const int mt  = cta >> 5;
    const int b0 = mt * 128, n0 = nt * 128;
    const int kslice = Ktot / NSPL;       // 80 (P1) or 128 (P2/P3)
    const int kbase0 = s * kslice;
    const int ntiles = kslice / KC;       // 5 or 8
    float* __restrict__ dst = dst_base + (size_t)s * BSZ * UU;
    const bool wb = (phase >= 2) && (nt == 0);

    const int fr = tid >> 1, fh = tid & 1;  // A-fill: row, half
    const int fk = tid >> 5, fc = tid & 31; // B-fill: kk, col-quad
    const int tr = tid >> 5, tc = tid & 31; // compute: warp row-group, col

    float* As = sm;             // dup-pair A
    float* Bs = sm + 2 * KC * 256;

    unsigned long long acc[16][2];
#pragma unroll
    for (int i = 0; i < 16; i++) { acc[i][0] = 0ULL; acc[i][1] = 0ULL; }

    float4 ra0, ra1, rb0, rb1;
    // prefetch tile 0
    ra0 = loadA(phase, b0 + fr, kbase0 + 4 * fh, t, x, wb);
    ra1 = loadA(phase, b0 + fr, kbase0 + 8 + 4 * fh, t, x, wb);
    rb0 = __ldg((const float4*)&W[(size_t)(kbase0 + fk) * UU + n0 + 4 * fc]);
    rb1 = __ldg((const float4*)&W[(size_t)(kbase0 + 8 + fk) * UU + n0 + 4 * fc]);

    {
        float* a = As + 2 * fr;
        *(float2*)(a + (4 * fh + 0) * 256) = make_float2(ra0.x, ra0.x);
        *(float2*)(a + (4 * fh + 1) * 256) = make_float2(ra0.y, ra0.y);
        *(float2*)(a + (4 * fh + 2) * 256) = make_float2(ra0.z, ra0.z);
        *(float2*)(a + (4 * fh + 3) * 256) = make_float2(ra0.w, ra0.w);
        *(float2*)(a + (8 + 4 * fh + 0) * 256) = make_float2(ra1.x, ra1.x);
        *(float2*)(a + (8 + 4 * fh + 1) * 256) = make_float2(ra1.y, ra1.y);
        *(float2*)(a + (8 + 4 * fh + 2) * 256) = make_float2(ra1.z, ra1.z);
        *(float2*)(a + (8 + 4 * fh + 3) * 256) = make_float2(ra1.w, ra1.w);
        *(float4*)(Bs + fk * 128 + 4 * fc) = rb0;
        *(float4*)(Bs + (8 + fk) * 128 + 4 * fc) = rb1;
    }
    __syncthreads();

    int buf = 0;
    for (int it = 0; it < ntiles; it++) {
        const bool more = (it + 1 < ntiles);
        if (more) {
            const int kb = kbase0 + (it + 1) * KC;
            ra0 = loadA(phase, b0 + fr, kb + 4 * fh, t, x, wb);
            ra1 = loadA(phase, b0 + fr, kb + 8 + 4 * fh, t, x, wb);
            rb0 = __ldg((const float4*)&W[(size_t)(kb + fk) * UU + n0 + 4 * fc]);
            rb1 = __ldg((const float4*)&W[(size_t)(kb + 8 + fk) * UU + n0 + 4 * fc]);
        }
        const float* ab = As + buf * (KC * 256) + 32 * tr;  // warp-uniform (broadcast)
        const float* bb = Bs + buf * (KC * 128) + 4 * tc;
#pragma unroll
        for (int kk = 0; kk < KC; kk++) {
            const ulonglong2 b2 = *(const ulonglong2*)(bb + kk * 128);
#pragma unroll
            for (int i = 0; i < 8; i++) {
                const ulonglong2 a2 = *(const ulonglong2*)(ab + kk * 256 + 4 * i);
                fma2(acc[2 * i + 0][0], a2.x, b2.x);
                fma2(acc[2 * i + 0][1], a2.x, b2.y);
                fma2(acc[2 * i + 1][0], a2.y, b2.x);
                fma2(acc[2 * i + 1][1], a2.y, b2.y);
            }
        }
        if (more) {
            const int nb = buf ^ 1;
            float* a = As + nb * (KC * 256) + 2 * fr;
            *(float2*)(a + (4 * fh + 0) * 256) = make_float2(ra0.x, ra0.x);
            *(float2*)(a + (4 * fh + 1) * 256) = make_float2(ra0.y, ra0.y);
            *(float2*)(a + (4 * fh + 2) * 256) = make_float2(ra0.z, ra0.z);
            *(float2*)(a + (4 * fh + 3) * 256) = make_float2(ra0.w, ra0.w);
            *(float2*)(a + (8 + 4 * fh + 0) * 256) = make_float2(ra1.x, ra1.x);
            *(float2*)(a + (8 + 4 * fh + 1) * 256) = make_float2(ra1.y, ra1.y);
            *(float2*)(a + (8 + 4 * fh + 2) * 256) = make_float2(ra1.z, ra1.z);
            *(float2*)(a + (8 + 4 * fh + 3) * 256) = make_float2(ra1.w, ra1.w);
            *(float4*)(Bs + nb * (KC * 128) + fk * 128 + 4 * fc) = rb0;
            *(float4*)(Bs + nb * (KC * 128) + (8 + fk) * 128 + 4 * fc) = rb1;
        }
        __syncthreads();
        buf ^= 1;
    }

    // epilogue: bias only on partial s==0 (merged sum gets it exactly once)
    float4 bias = make_float4(0.f, 0.f, 0.f, 0.f);
    if (s == 0) bias = __ldg((const float4*)&cb[n0 + 4 * tc]);
#pragma unroll
    for (int r = 0; r < 16; r++) {
        float x0, x1, x2, x3;
        unpack2(acc[r][0], x0, x1);
        unpack2(acc[r][1], x2, x3);
        *(float4*)&dst[(size_t)(b0 + 16 * tr + r) * UU + n0 + 4 * tc] =
            make_float4(x0 + bias.x, x1 + bias.y, x2 + bias.z, x3 + bias.w);
    }
}

// ---------------- phase 4: merge ns2, res = ns2@Eo + co, acc += res ---------
__device__ void phase4(float* sm, int t, float* __restrict__ out) {
    const int tid = threadIdx.x;
    const int b0 = blockIdx.x * 4;      // 4 batch rows per CTA
    float* Hs = sm;                      // 2048 floats, aliases GEMM smem
#pragma unroll
    for (int j = 0; j < 2; j++) {
        const int fi = tid + j * 256;    // float4 index in [0,512)
        const int off = b0 * UU + fi * 4;
        float4 v = __ldcg((const float4*)&g_NS[2][0][off]);
#pragma unroll
        for (int s = 1; s < NSPL; s++) {
            const float4 w = __ldcg((const float4*)&g_NS[2][s][off]);
            v.x += w.x; v.y += w.y; v.z += w.z; v.w += w.w;
        }
        *(float4*)&g_HM[2][off] = v;     // piggyback merge -> hs2 for next step
        *(float4*)&Hs[fi * 4] = v;
    }
    __syncthreads();
    if (tid < 128) {
        const int r = tid >> 5, c = tid & 31;
        const float* h = Hs + r * UU;    // warp-uniform (broadcast)
        float s0 = 0.f, s1 = 0.f, s2 = 0.f, s3 = 0.f;
#pragma unroll 4
        for (int k = 0; k < UU; k += 4) {
            s0 = fmaf(h[k + 0], __ldg(&g_Wo[(k + 0) * PP + c]), s0);
            s1 = fmaf(h[k + 1], __ldg(&g_Wo[(k + 1) * PP + c]), s1);
            s2 = fmaf(h[k + 2], __ldg(&g_Wo[(k + 2) * PP + c]), s2);
            s3 = fmaf(h[k + 3], __ldg(&g_Wo[(k + 3) * PP + c]), s3);
        }
        const float res = (s0 + s1) + (s2 + s3) + __ldg(&g_co[c]);
        const int b = b0 + r;
        g_ACC[b * PP + c] = __ldcg(&g_ACC[b * PP + c]) + res;
        out[((size_t)b * TSZ + t) * PP + c] = res;
    }
    __syncthreads();
}

// ---------------- persistent time loop ----------------
__global__ void __launch_bounds__(NTHR, 1)
rnn_run(const float* __restrict__ x, float* __restrict__ out) {
    __shared__ float sm[12288];          // exactly 48 KB
    unsigned barn = 0;
    for (int t = 0; t < TSZ; t++) {
        phase_gemm(sm, 1, t, x, g_W0, g_c0, K1P,    &g_NS[0][0][0]);
        gsync(barn);
        phase_gemm(sm, 2, t, x, g_W1, g_c1, 2 * UU, &g_NS[1][0][0]);
        gsync(barn);
        phase_gemm(sm, 3, t, x, g_W2, g_c2, 2 * UU, &g_NS[2][0][0]);
        gsync(barn);
        phase4(sm, t, out);
        gsync(barn);
    }
}

// ---------------- setup (fused to keep launch count = 6, rnn last) ---------
__global__ void pack_init(const float* __restrict__ WA, const float* __restrict__ WB0) {
    const size_t tid = (size_t)blockIdx.x * blockDim.x + threadIdx.x;
    const size_t stride = (size_t)gridDim.x * blockDim.x;
    for (size_t i = tid; i < (size_t)K1P * UU; i += stride) {
        const int k = (int)(i >> 9), n = (int)(i & 511);
        float v;
        if (k < UU) v = WA[(size_t)k * UU + n];
        else if (k < UU + FF + PP) v = WB0[(size_t)(k - UU) * UU + n];
        else v = 0.f;
        g_W0[i] = v;
    }
    for (size_t i = tid; i < (size_t)UU * UU; i += stride) {
        g_W1[i] = WA[(size_t)UU * UU + i];
        g_W2[i] = WA[(size_t)2 * UU * UU + i];
    }
    for (size_t i = tid; i < (size_t)3 * BSZ * UU; i += stride) (&g_HM[0][0])[i] = 0.f;
    for (size_t i = tid; i < (size_t)BSZ * PP; i += stride) g_ACC[i] = 0.f;
    if (tid == 0) g_bar = 0u;
}

// which: 0 -> E1 into g_W1[512:], 1 -> E2 into g_W2[512:], 2 -> Eo into g_Wo
__global__ void gemm_pre(const float* __restrict__ A, const float* __restrict__ Bm, int which) {
    float* C = (which == 0) ? g_W1 + UU * UU : (which == 1) ? g_W2 + UU * UU : g_Wo;
    const int N = (which == 2) ? PP : UU;
    __shared__ float As_[32][33], Bs_[32][33];
    const int tx = threadIdx.x, ty = threadIdx.y;
    const int row = blockIdx.y * 32 + ty;
    const int col = blockIdx.x * 32 + tx;
    float s = 0.f;
    for (int k0 = 0; k0 < UU; k0 += 32) {
        As_[ty][tx] = A[(size_t)row * UU + k0 + tx];
        Bs_[ty][tx] = (col < N) ? Bm[(size_t)(k0 + ty) * N + col] : 0.f;
        __syncthreads();
#pragma unroll
        for (int kk = 0; kk < 32; kk++) s = fmaf(As_[ty][kk], Bs_[kk][tx], s);
        __syncthreads();
    }
    if (col < N) C[(size_t)row * N + col] = s;
}

__global__ void make_biases(const float* __restrict__ bA, const float* __restrict__ bB0,
                            const float* __restrict__ bBr, const float* __restrict__ bC,
                            const float* __restrict__ WBr, const float* __restrict__ Wout,
                            const float* __restrict__ bout) {
    const int j = threadIdx.x;
    if (j < UU) {
        g_c0[j] = bA[j] + bB0[j];
        float s1 = 0.f, s2 = 0.f;
        for (int k = 0; k < UU; k++) {
            s1 = fmaf(bC[k], WBr[(size_t)k * UU + j], s1);
            s2 = fmaf(bC[UU + k], WBr[(size_t)UU * UU + (size_t)k * UU + j], s2);
        }
        g_c1[j] = bA[UU + j] + bBr[j] + s1;
        g_c2[j] = bA[2 * UU + j] + bBr[UU + j] + s2;
    }
    if (j < PP) {
        float s = 0.f;
        for (int k = 0; k < UU; k++) s = fmaf(bC[2 * UU + k], Wout[(size_t)k * PP + j], s);
        g_co[j] = bout[j] + s;
    }
}

// ---------------- entry: exactly 6 launches, rnn_run last ----------------
extern "C" void kernel_launch(void* const* d_in, const int* in_sizes, int n_in,
                              void* d_out, int out_size) {
    const float* x    = (const float*)d_in[0];
    const float* WA   = (const float*)d_in[1];
    const float* bA   = (const float*)d_in[2];
    const float* WB0  = (const float*)d_in[3];
    const float* bB0  = (const float*)d_in[4];
    const float* WBr  = (const float*)d_in[5];
    const float* bBr  = (const float*)d_in[6];
    const float* WC   = (const float*)d_in[7];
    const float* bC   = (const float*)d_in[8];
    const float* Wout = (const float*)d_in[9];
    const float* bout = (const float*)d_in[10];
    float* out = (float*)d_out;

    pack_init<<<256, 256>>>(WA, WB0);

    dim3 blk(32, 32);
    gemm_pre<<<dim3(16, 16), blk>>>(WC,               WBr,           0);
    gemm_pre<<<dim3(16, 16), blk>>>(WC + UU * UU,     WBr + UU * UU, 1);
    gemm_pre<<<dim3(1, 16),  blk>>>(WC + 2 * UU * UU, Wout,          2);

    make_biases<<<1, 512>>>(bA, bB0, bBr, bC, WBr, Wout, bout);

    rnn_run<<<NCTA, NTHR>>>(x, out);
}

// round 5
// speedup vs baseline: 1.6020x; 1.6020x over previous
#include <cuda_runtime.h>
#include <cstdint>

#define BSZ 512
#define TSZ 512
#define FF  64
#define UU  512
#define PP  32
#define K1P 640                 // 512 hs | 64 x | 32 acc | 32 zero-pad
#define NCTA 128
#define NTHR 256
#define KC   16
#define NSPL 8                  // split-K factor

// ---------------- device-global scratch ----------------
__device__ float g_W0[K1P * UU];       // [640,512] rows: WA0 | WB0(x) | WB0(acc) | 0
__device__ float g_W1[2 * UU * UU];    // rows 0-511 WA1, 512-1023 E1=WC0@WBr0
__device__ float g_W2[2 * UU * UU];    // rows 0-511 WA2, 512-1023 E2=WC1@WBr1
__device__ float g_Wo[UU * PP];        // Eo = WC2@Wout
__device__ float g_c0[UU], g_c1[UU], g_c2[UU], g_co[PP];
__device__ float g_NS[3][NSPL][BSZ * UU];  // split-K partials per layer
__device__ float g_HM[3][BSZ * UU];        // merged states (= hs for next step)
__device__ float g_ACC[BSZ * PP];
__device__ unsigned g_bar;

// ---------------- FFMA2 helpers ----------------
__device__ __forceinline__ void fma2(unsigned long long& d, unsigned long long a,
                                     unsigned long long b) {
    asm("fma.rn.f32x2 %0, %1, %2, %0;" : "+l"(d) : "l"(a), "l"(b));
}
__device__ __forceinline__ void unpack2(unsigned long long v, float& lo, float& hi) {
    asm("mov.b64 {%0, %1}, %2;" : "=f"(lo), "=f"(hi) : "l"(v));
}

// ---------------- grid barrier (128 CTAs, single wave) ----------------
// arrival: one release-reduction per CTA; wait: acquire-load spin (no sleep)
__device__ __forceinline__ void gsync(unsigned& barn) {
    barn += 1;
    const unsigned target = barn * NCTA;
    __syncthreads();
    if (threadIdx.x == 0) {
        asm volatile("red.release.gpu.global.add.u32 [%0], 1;"
                     :: "l"(&g_bar) : "memory");
        unsigned v;
        do {
            asm volatile("ld.acquire.gpu.u32 %0, [%1];" : "=r"(v) : "l"(&g_bar) : "memory");
        } while (v < target);
    }
    __syncthreads();
}

// ---------------- A-operand fetch (merged across split-K partials) ----------
__device__ __forceinline__ float4 loadA(int phase, int b, int k, int t,
                                        const float* __restrict__ x, bool wb) {
    float4 v;
    if (phase == 1) {
        if (k < UU)
            v = __ldcg((const float4*)&g_HM[0][b * UU + k]);
        else if (k < UU + FF)
            v = __ldg((const float4*)&x[((size_t)b * TSZ + t) * FF + (k - UU)]);
        else if (k < UU + FF + PP)
            v = __ldcg((const float4*)&g_ACC[b * PP + (k - UU - FF)]);
        else
            v = make_float4(0.f, 0.f, 0.f, 0.f);
    } else {
        if (k < UU) {
            v = __ldcg((const float4*)&g_HM[phase - 1][b * UU + k]);
        } else {
            const int off = b * UU + (k - UU);
            const float(*P)[BSZ * UU] = g_NS[phase - 2];
            v = __ldcg((const float4*)&P[0][off]);
#pragma unroll
            for (int s = 1; s < NSPL; s++) {
                const float4 w = __ldcg((const float4*)&P[s][off]);
                v.x += w.x; v.y += w.y; v.z += w.z; v.w += w.w;
            }
            if (wb) *(float4*)&g_HM[phase - 2][off] = v;  // piggyback merge
        }
    }
    return v;
}

// ---------------- main GEMM phase: tile 128x128, split-K 8 ------------------
// smem: As2 [2][KC][256] dup pairs (8192 f) then Bs [2][KC][128] (4096 f)
__device__ void phase_gemm(float* sm, int phase, int t, const float* __restrict__ x,
                           const float* __restrict__ W, const float* __restrict__ cb,
                           int Ktot, float* __restrict__ dst_base) {
    const int tid = threadIdx.x;
    const int cta = blockIdx.x;
    const int s   = cta & 7;
    const int nt  = (cta >> 3) & 3;
    const int mt  = cta >> 5;
    const int b0 = mt * 128, n0 = nt * 128;
    const int kslice = Ktot / NSPL;       // 80 (P1) or 128 (P2/P3)
    const int kbase0 = s * kslice;
    const int ntiles = kslice / KC;       // 5 or 8
    float* __restrict__ dst = dst_base + (size_t)s * BSZ * UU;
    const bool wb = (phase >= 2) && (nt == 0);

    const int fr = tid >> 1, fh = tid & 1;  // A-fill: row, half
    const int fk = tid >> 5, fc = tid & 31; // B-fill: kk, col-quad
    const int tr = tid >> 5, tc = tid & 31; // compute: warp row-group, col

    float* As = sm;             // dup-pair A
    float* Bs = sm + 2 * KC * 256;

    unsigned long long acc[16][2];
#pragma unroll
    for (int i = 0; i < 16; i++) { acc[i][0] = 0ULL; acc[i][1] = 0ULL; }

    float4 ra0, ra1, rb0, rb1;
    // prefetch tile 0
    ra0 = loadA(phase, b0 + fr, kbase0 + 4 * fh, t, x, wb);
    ra1 = loadA(phase, b0 + fr, kbase0 + 8 + 4 * fh, t, x, wb);
    rb0 = __ldg((const float4*)&W[(size_t)(kbase0 + fk) * UU + n0 + 4 * fc]);
    rb1 = __ldg((const float4*)&W[(size_t)(kbase0 + 8 + fk) * UU + n0 + 4 * fc]);

    {
        float* a = As + 2 * fr;
        *(float2*)(a + (4 * fh + 0) * 256) = make_float2(ra0.x, ra0.x);
        *(float2*)(a + (4 * fh + 1) * 256) = make_float2(ra0.y, ra0.y);
        *(float2*)(a + (4 * fh + 2) * 256) = make_float2(ra0.z, ra0.z);
        *(float2*)(a + (4 * fh + 3) * 256) = make_float2(ra0.w, ra0.w);
        *(float2*)(a + (8 + 4 * fh + 0) * 256) = make_float2(ra1.x, ra1.x);
        *(float2*)(a + (8 + 4 * fh + 1) * 256) = make_float2(ra1.y, ra1.y);
        *(float2*)(a + (8 + 4 * fh + 2) * 256) = make_float2(ra1.z, ra1.z);
        *(float2*)(a + (8 + 4 * fh + 3) * 256) = make_float2(ra1.w, ra1.w);
        *(float4*)(Bs + fk * 128 + 4 * fc) = rb0;
        *(float4*)(Bs + (8 + fk) * 128 + 4 * fc) = rb1;
    }
    __syncthreads();

    int buf = 0;
    for (int it = 0; it < ntiles; it++) {
        const bool more = (it + 1 < ntiles);
        if (more) {
            const int kb = kbase0 + (it + 1) * KC;
            ra0 = loadA(phase, b0 + fr, kb + 4 * fh, t, x, wb);
            ra1 = loadA(phase, b0 + fr, kb + 8 + 4 * fh, t, x, wb);
            rb0 = __ldg((const float4*)&W[(size_t)(kb + fk) * UU + n0 + 4 * fc]);
            rb1 = __ldg((const float4*)&W[(size_t)(kb + 8 + fk) * UU + n0 + 4 * fc]);
        }
        const float* ab = As + buf * (KC * 256) + 32 * tr;  // warp-uniform (broadcast)
        const float* bb = Bs + buf * (KC * 128) + 4 * tc;
#pragma unroll
        for (int kk = 0; kk < KC; kk++) {
            const ulonglong2 b2 = *(const ulonglong2*)(bb + kk * 128);
#pragma unroll
            for (int i = 0; i < 8; i++) {
                const ulonglong2 a2 = *(const ulonglong2*)(ab + kk * 256 + 4 * i);
                fma2(acc[2 * i + 0][0], a2.x, b2.x);
                fma2(acc[2 * i + 0][1], a2.x, b2.y);
                fma2(acc[2 * i + 1][0], a2.y, b2.x);
                fma2(acc[2 * i + 1][1], a2.y, b2.y);
            }
        }
        if (more) {
            const int nb = buf ^ 1;
            float* a = As + nb * (KC * 256) + 2 * fr;
            *(float2*)(a + (4 * fh + 0) * 256) = make_float2(ra0.x, ra0.x);
            *(float2*)(a + (4 * fh + 1) * 256) = make_float2(ra0.y, ra0.y);
            *(float2*)(a + (4 * fh + 2) * 256) = make_float2(ra0.z, ra0.z);
            *(float2*)(a + (4 * fh + 3) * 256) = make_float2(ra0.w, ra0.w);
            *(float2*)(a + (8 + 4 * fh + 0) * 256) = make_float2(ra1.x, ra1.x);
            *(float2*)(a + (8 + 4 * fh + 1) * 256) = make_float2(ra1.y, ra1.y);
            *(float2*)(a + (8 + 4 * fh + 2) * 256) = make_float2(ra1.z, ra1.z);
            *(float2*)(a + (8 + 4 * fh + 3) * 256) = make_float2(ra1.w, ra1.w);
            *(float4*)(Bs + nb * (KC * 128) + fk * 128 + 4 * fc) = rb0;
            *(float4*)(Bs + nb * (KC * 128) + (8 + fk) * 128 + 4 * fc) = rb1;
        }
        __syncthreads();
        buf ^= 1;
    }

    // epilogue: bias only on partial s==0 (merged sum gets it exactly once)
    float4 bias = make_float4(0.f, 0.f, 0.f, 0.f);
    if (s == 0) bias = __ldg((const float4*)&cb[n0 + 4 * tc]);
#pragma unroll
    for (int r = 0; r < 16; r++) {
        float x0, x1, x2, x3;
        unpack2(acc[r][0], x0, x1);
        unpack2(acc[r][1], x2, x3);
        *(float4*)&dst[(size_t)(b0 + 16 * tr + r) * UU + n0 + 4 * tc] =
            make_float4(x0 + bias.x, x1 + bias.y, x2 + bias.z, x3 + bias.w);
    }
}

// ---------------- phase 4: merge ns2, res = ns2@Eo + co, acc += res ---------
__device__ void phase4(float* sm, int t, float* __restrict__ out) {
    const int tid = threadIdx.x;
    const int b0 = blockIdx.x * 4;      // 4 batch rows per CTA
    float* Hs = sm;                      // 2048 floats, aliases GEMM smem
#pragma unroll
    for (int j = 0; j < 2; j++) {
        const int fi = tid + j * 256;    // float4 index in [0,512)
        const int off = b0 * UU + fi * 4;
        float4 v = __ldcg((const float4*)&g_NS[2][0][off]);
#pragma unroll
        for (int s = 1; s < NSPL; s++) {
            const float4 w = __ldcg((const float4*)&g_NS[2][s][off]);
            v.x += w.x; v.y += w.y; v.z += w.z; v.w += w.w;
        }
        *(float4*)&g_HM[2][off] = v;     // piggyback merge -> hs2 for next step
        *(float4*)&Hs[fi * 4] = v;
    }
    __syncthreads();
    if (tid < 128) {
        const int r = tid >> 5, c = tid & 31;
        const float* h = Hs + r * UU;    // warp-uniform (broadcast)
        float s0 = 0.f, s1 = 0.f, s2 = 0.f, s3 = 0.f;
#pragma unroll 4
        for (int k = 0; k < UU; k += 4) {
            s0 = fmaf(h[k + 0], __ldg(&g_Wo[(k + 0) * PP + c]), s0);
            s1 = fmaf(h[k + 1], __ldg(&g_Wo[(k + 1) * PP + c]), s1);
            s2 = fmaf(h[k + 2], __ldg(&g_Wo[(k + 2) * PP + c]), s2);
            s3 = fmaf(h[k + 3], __ldg(&g_Wo[(k + 3) * PP + c]), s3);
        }
        const float res = (s0 + s1) + (s2 + s3) + __ldg(&g_co[c]);
        const int b = b0 + r;
        g_ACC[b * PP + c] = __ldcg(&g_ACC[b * PP + c]) + res;
        out[((size_t)b * TSZ + t) * PP + c] = res;
    }
    __syncthreads();
}

// ---------------- persistent time loop over a segment [t0,t1) --------------
__global__ void __launch_bounds__(NTHR, 1)
rnn_run(const float* __restrict__ x, float* __restrict__ out, int t0, int t1) {
    __shared__ float sm[12288];          // exactly 48 KB
    unsigned barn = (unsigned)t0 * 4;    // barrier epoch continues across segments
    for (int t = t0; t < t1; t++) {
        phase_gemm(sm, 1, t, x, g_W0, g_c0, K1P,    &g_NS[0][0][0]);
        gsync(barn);
        phase_gemm(sm, 2, t, x, g_W1, g_c1, 2 * UU, &g_NS[1][0][0]);
        gsync(barn);
        phase_gemm(sm, 3, t, x, g_W2, g_c2, 2 * UU, &g_NS[2][0][0]);
        gsync(barn);
        phase4(sm, t, out);
        gsync(barn);
    }
}

// ---------------- setup ----------------
__global__ void pack_init(const float* __restrict__ WA, const float* __restrict__ WB0) {
    const size_t tid = (size_t)blockIdx.x * blockDim.x + threadIdx.x;
    const size_t stride = (size_t)gridDim.x * blockDim.x;
    for (size_t i = tid; i < (size_t)K1P * UU; i += stride) {
        const int k = (int)(i >> 9), n = (int)(i & 511);
        float v;
        if (k < UU) v = WA[(size_t)k * UU + n];
        else if (k < UU + FF + PP) v = WB0[(size_t)(k - UU) * UU + n];
        else v = 0.f;
        g_W0[i] = v;
    }
    for (size_t i = tid; i < (size_t)UU * UU; i += stride) {
        g_W1[i] = WA[(size_t)UU * UU + i];
        g_W2[i] = WA[(size_t)2 * UU * UU + i];
    }
    for (size_t i = tid; i < (size_t)3 * BSZ * UU; i += stride) (&g_HM[0][0])[i] = 0.f;
    for (size_t i = tid; i < (size_t)BSZ * PP; i += stride) g_ACC[i] = 0.f;
    if (tid == 0) g_bar = 0u;
}

// fused: z=0 -> E1 into g_W1[512:], z=1 -> E2 into g_W2[512:], z=2 -> Eo into g_Wo
__global__ void gemm_pre_all(const float* __restrict__ WC, const float* __restrict__ WBr,
                             const float* __restrict__ Wout) {
    const int which = blockIdx.z;
    if (which == 2 && blockIdx.x > 0) return;
    const float* A  = WC + (size_t)which * UU * UU;
    const float* Bm = (which == 0) ? WBr : (which == 1) ? (WBr + UU * UU) : Wout;
    float* C = (which == 0) ? g_W1 + UU * UU : (which == 1) ? g_W2 + UU * UU : g_Wo;
    const int N = (which == 2) ? PP : UU;
    __shared__ float As_[32][33], Bs_[32][33];
    const int tx = threadIdx.x, ty = threadIdx.y;
    const int row = blockIdx.y * 32 + ty;
    const int col = blockIdx.x * 32 + tx;
    float s = 0.f;
    for (int k0 = 0; k0 < UU; k0 += 32) {
        As_[ty][tx] = A[(size_t)row * UU + k0 + tx];
        Bs_[ty][tx] = (col < N) ? Bm[(size_t)(k0 + ty) * N + col] : 0.f;
        __syncthreads();
#pragma unroll
        for (int kk = 0; kk < 32; kk++) s = fmaf(As_[ty][kk], Bs_[kk][tx], s);
        __syncthreads();
    }
    if (col < N) C[(size_t)row * N + col] = s;
}

__global__ void make_biases(const float* __restrict__ bA, const float* __restrict__ bB0,
                            const float* __restrict__ bBr, const float* __restrict__ bC,
                            const float* __restrict__ WBr, const float* __restrict__ Wout,
                            const float* __restrict__ bout) {
    const int j = threadIdx.x;
    if (j < UU) {
        g_c0[j] = bA[j] + bB0[j];
        float s1 = 0.f, s2 = 0.f;
        for (int k = 0; k < UU; k++) {
            s1 = fmaf(bC[k], WBr[(size_t)k * UU + j], s1);
            s2 = fmaf(bC[UU + k], WBr[(size_t)UU * UU + (size_t)k * UU + j], s2);
        }
        g_c1[j] = bA[UU + j] + bBr[j] + s1;
        g_c2[j] = bA[2 * UU + j] + bBr[UU + j] + s2;
    }
    if (j < PP) {
        float s = 0.f;
        for (int k = 0; k < UU; k++) s = fmaf(bC[2 * UU + k], Wout[(size_t)k * PP + j], s);
        g_co[j] = bout[j] + s;
    }
}

// ---------------- entry: launches #4,#5,#6 are all rnn_run segments --------
extern "C" void kernel_launch(void* const* d_in, const int* in_sizes, int n_in,
                              void* d_out, int out_size) {
    const float* x    = (const float*)d_in[0];
    const float* WA   = (const float*)d_in[1];
    const float* bA   = (const float*)d_in[2];
    const float* WB0  = (const float*)d_in[3];
    const float* bB0  = (const float*)d_in[4];
    const float* WBr  = (const float*)d_in[5];
    const float* bBr  = (const float*)d_in[6];
    const float* WC   = (const float*)d_in[7];
    const float* bC   = (const float*)d_in[8];
    const float* Wout = (const float*)d_in[9];
    const float* bout = (const float*)d_in[10];
    float* out = (float*)d_out;

    pack_init<<<256, 256>>>(WA, WB0);                                   // #1
    gemm_pre_all<<<dim3(16, 16, 3), dim3(32, 32)>>>(WC, WBr, Wout);     // #2
    make_biases<<<1, 512>>>(bA, bB0, bBr, bC, WBr, Wout, bout);         // #3
    rnn_run<<<NCTA, NTHR>>>(x, out, 0, 171);                            // #4
    rnn_run<<<NCTA, NTHR>>>(x, out, 171, 342);                          // #5
    rnn_run<<<NCTA, NTHR>>>(x, out, 342, 512);                          // #6
}